// round 12
// baseline (speedup 1.0000x reference)
#include <cuda_runtime.h>
#include <cuda_bf16.h>
#include <cstdint>

// Problem constants: B=4, H=16, S=2048, D=64
#define S_LEN 2048
#define DH    64
#define BHN   64
#define BQ    64            // query rows per CTA
#define BKT   64            // key rows per tile
#define NTILE 32
#define NELEM ((size_t)BHN * S_LEN * DH)   // 8388608

// smem: Q hi/lo [64x64] + ring region
//  pass A: 4 stages x 8KB (KH only)
//  pass B: 3 slots x 32KB; K half {KH,KL} at +0, V half {VH,VL} at +16384
//          V reads lag K by one tile (slot (t-1)%3)
#define OFF_QH 0
#define OFF_QL 8192
#define OFF_ST 16384
#define SMEM_SZ (16384 + 3 * 32768)   // 114688
// post-hoist reuse of the (dead) Q region
#define OFF_RS  0           // float rsum[2][64]
#define OFF_INV 512         // float inv_s[64]
#define OFF_OSM 16384       // float Osm[64][64] (tail only)

typedef unsigned long long ull;

// pre-split bf16 hi/lo copies of q,k,v + bit-packed mask
__device__ __align__(16) uint2 g_qhi[NELEM / 4], g_qlo[NELEM / 4];
__device__ __align__(16) uint2 g_khi[NELEM / 4], g_klo[NELEM / 4];
__device__ __align__(16) uint2 g_vhi[NELEM / 4], g_vlo[NELEM / 4];
__device__ uint32_t g_mbits[(size_t)S_LEN * (S_LEN / 32)];   // [row][word]

// ---------------- helpers ----------------
__device__ __forceinline__ uint32_t s2u(const void* p) {
    uint32_t a;
    asm("{ .reg .u64 t; cvta.to.shared.u64 t, %1; cvt.u32.u64 %0, t; }" : "=r"(a) : "l"(p));
    return a;
}
__device__ __forceinline__ void ldsm4(uint32_t a, uint32_t* r) {
    asm volatile("ldmatrix.sync.aligned.m8n8.x4.shared.b16 {%0,%1,%2,%3}, [%4];"
                 : "=r"(r[0]), "=r"(r[1]), "=r"(r[2]), "=r"(r[3]) : "r"(a));
}
__device__ __forceinline__ void ldsm4t(uint32_t a, uint32_t* r) {
    asm volatile("ldmatrix.sync.aligned.m8n8.x4.trans.shared.b16 {%0,%1,%2,%3}, [%4];"
                 : "=r"(r[0]), "=r"(r[1]), "=r"(r[2]), "=r"(r[3]) : "r"(a));
}
__device__ __forceinline__ void mma_bf16(float* d, const uint32_t* a,
                                         uint32_t b0, uint32_t b1) {
    asm volatile("mma.sync.aligned.m16n8k16.row.col.f32.bf16.bf16.f32 "
                 "{%0,%1,%2,%3},{%4,%5,%6,%7},{%8,%9},{%0,%1,%2,%3};"
                 : "+f"(d[0]), "+f"(d[1]), "+f"(d[2]), "+f"(d[3])
                 : "r"(a[0]), "r"(a[1]), "r"(a[2]), "r"(a[3]), "r"(b0), "r"(b1));
}
__device__ __forceinline__ uint32_t pk2(float lo, float hi) {
    uint32_t r;
    asm("cvt.rn.bf16x2.f32 %0, %1, %2;" : "=r"(r) : "f"(hi), "f"(lo));
    return r;
}
__device__ __forceinline__ float lo16f(uint32_t u) { return __uint_as_float(u << 16); }
__device__ __forceinline__ float hi16f(uint32_t u) { return __uint_as_float(u & 0xFFFF0000u); }

__device__ __forceinline__ void cpa16(uint32_t dst, const void* src) {
    asm volatile("cp.async.cg.shared.global [%0], [%1], 16;" :: "r"(dst), "l"(src));
}
#define CPA_COMMIT() asm volatile("cp.async.commit_group;" ::: "memory")
#define CPA_WAIT2()  asm volatile("cp.async.wait_group 2;" ::: "memory")
#define CPA_WAIT1()  asm volatile("cp.async.wait_group 1;" ::: "memory")
#define CPA_WAIT0()  asm volatile("cp.async.wait_group 0;" ::: "memory")

// ---------------- pre-pass kernels ----------------
__global__ __launch_bounds__(256) void presplit(const float4* __restrict__ src,
                                                uint2* __restrict__ dhi,
                                                uint2* __restrict__ dlo)
{
    int i = blockIdx.x * blockDim.x + threadIdx.x;
    float4 t = src[i];
    uint32_t h01 = pk2(t.x, t.y), h23 = pk2(t.z, t.w);
    uint32_t l01 = pk2(t.x - lo16f(h01), t.y - hi16f(h01));
    uint32_t l23 = pk2(t.z - lo16f(h23), t.w - hi16f(h23));
    dhi[i] = make_uint2(h01, h23);
    dlo[i] = make_uint2(l01, l23);
}

__global__ __launch_bounds__(256) void pmask(const int* __restrict__ mask,
                                             uint32_t* __restrict__ bits)
{
    int idx = blockIdx.x * blockDim.x + threadIdx.x;   // word index
    const int4* m4 = (const int4*)mask + (size_t)idx * 8;
    uint32_t b = 0;
    #pragma unroll
    for (int i = 0; i < 8; ++i) {
        int4 v = m4[i];
        b |= (v.x != 0 ? 1u : 0u) << (i * 4);
        b |= (v.y != 0 ? 1u : 0u) << (i * 4 + 1);
        b |= (v.z != 0 ? 1u : 0u) << (i * 4 + 2);
        b |= (v.w != 0 ? 1u : 0u) << (i * 4 + 3);
    }
    bits[idx] = b;
}

__global__ __launch_bounds__(256, 2)
void attn_mma(float* __restrict__ out, float* __restrict__ p)
{
    extern __shared__ char sm[];
    const uint32_t sb = s2u(sm);
    const int tid = threadIdx.x;
    const int wid = tid >> 5, lane = tid & 31;
    const int rg = wid >> 1;                 // row group (16 rows)
    const int nhalf = wid & 1;               // 32-col half of tile
    const int bh = blockIdx.y;
    const int q0 = blockIdx.x * BQ;

    // cp.async mapping: chunk cc (16B), rows rr, rr+32
    const int cc = tid & 7, rr = tid >> 3;
    const uint32_t dcol = ((uint32_t)cc) << 4;
    const uint32_t drow0 = (uint32_t)rr * 128 + (dcol ^ (((uint32_t)rr & 7) << 4));
    const uint32_t drow1 = (uint32_t)(rr + 32) * 128 + (dcol ^ ((((uint32_t)rr + 32) & 7) << 4));
    const size_t srow0 = (size_t)rr * 128 + cc * 16;
    const size_t srow1 = (size_t)(rr + 32) * 128 + cc * 16;

    const char* khb = (const char*)g_khi + (size_t)bh * S_LEN * 128;
    const char* klb = (const char*)g_klo + (size_t)bh * S_LEN * 128;
    const char* vhb = (const char*)g_vhi + (size_t)bh * S_LEN * 128;
    const char* vlb = (const char*)g_vlo + (size_t)bh * S_LEN * 128;

    // epilogue thread mapping (m16n8 accum layout)
    const int r0l = rg * 16 + (lane >> 2);
    const int coff = (lane & 3) * 2;

    // ldmatrix lane mappings (XOR applied AFTER column adds)
    const int arow = rg * 16 + (lane & 15);
    const uint32_t arowoff = (uint32_t)arow * 128;
    const uint32_t acol0 = ((uint32_t)(lane >> 4)) << 4;
    const uint32_t axor = ((uint32_t)arow & 7) << 4;
    const int nrow = ((lane >> 4) << 3) + (lane & 7);
    const uint32_t nbase = (uint32_t)(nhalf * 32 + nrow) * 128;
    const uint32_t ncol0 = (((uint32_t)lane >> 3) & 1) << 4;
    const uint32_t nxor = ((uint32_t)(nrow & 7)) << 4;
    const int vrow = (((lane >> 3) & 1) << 3) + (lane & 7);
    const uint32_t vbase_off = (uint32_t)(nhalf * 32 + vrow) * 128;
    const uint32_t vcol0 = ((uint32_t)(lane >> 4)) << 4;
    const uint32_t vxor = ((uint32_t)(vrow & 7)) << 4;

    const uint32_t* mb0 = g_mbits + (size_t)(q0 + r0l) * 64 + nhalf;
    const uint32_t* mb1 = mb0 + 8 * 64;

    // ===== prologue: Q + pass-A 4-stage KH ring prime (3 commits) =====
    {
        const char* qh = (const char*)g_qhi + ((size_t)bh * S_LEN + q0) * 128;
        const char* ql = (const char*)g_qlo + ((size_t)bh * S_LEN + q0) * 128;
        cpa16(sb + OFF_QH + drow0, qh + srow0);
        cpa16(sb + OFF_QH + drow1, qh + srow1);
        cpa16(sb + OFF_QL + drow0, ql + srow0);
        cpa16(sb + OFF_QL + drow1, ql + srow1);
        cpa16(sb + OFF_ST + drow0, khb + srow0);
        cpa16(sb + OFF_ST + drow1, khb + srow1);
        CPA_COMMIT();
        #pragma unroll
        for (int s = 1; s < 3; ++s) {
            const uint32_t st = sb + OFF_ST + (uint32_t)s * 8192;
            const size_t tb = (size_t)s * BKT * 128;
            cpa16(st + drow0, khb + tb + srow0);
            cpa16(st + drow1, khb + tb + srow1);
            CPA_COMMIT();
        }
    }
    CPA_WAIT2();          // Q + stage0 complete
    __syncthreads();

    // ---- hoist Q fragments (tile-invariant) into registers
    uint32_t qah[4][4], qal[4][4];
    #pragma unroll
    for (int ks = 0; ks < 4; ++ks) {
        const uint32_t ao = arowoff + ((acol0 + (uint32_t)ks * 32) ^ axor);
        ldsm4(sb + OFF_QH + ao, qah[ks]);
        ldsm4(sb + OFF_QL + ao, qal[ks]);
    }

    float esum0 = 0.f, esum1 = 0.f;

    // ===== PASS A: approximate row sums (Qh.Kh only; ~4e-4 rel err on l) =====
    for (int kb = 0; kb < NTILE; ++kb) {
        if (kb) { CPA_WAIT2(); __syncthreads(); }
        const uint32_t st = sb + OFF_ST + (uint32_t)(kb & 3) * 8192;
        const uint32_t w0 = mb0[kb * 2];
        const uint32_t w1 = mb1[kb * 2];

        float acc[4][4];
        #pragma unroll
        for (int i = 0; i < 4; ++i)
            #pragma unroll
            for (int c = 0; c < 4; ++c) acc[i][c] = 0.f;

        #pragma unroll
        for (int ks = 0; ks < 4; ++ks) {
            #pragma unroll
            for (int np = 0; np < 2; ++np) {
                uint32_t bh4[4];
                const uint32_t bo = nbase + (uint32_t)np * 2048 +
                                    ((ncol0 + (uint32_t)ks * 32) ^ nxor);
                ldsm4(st + bo, bh4);
                mma_bf16(acc[np * 2], qah[ks], bh4[0], bh4[1]);
                mma_bf16(acc[np * 2 + 1], qah[ks], bh4[2], bh4[3]);
            }
        }

        #pragma unroll
        for (int nt = 0; nt < 4; ++nt) {
            const int sh = coff + nt * 8;
            esum0 += ((w0 >> sh) & 1 ? __expf(acc[nt][0] * 0.125f) : 0.f)
                   + ((w0 >> (sh + 1)) & 1 ? __expf(acc[nt][1] * 0.125f) : 0.f);
            esum1 += ((w1 >> sh) & 1 ? __expf(acc[nt][2] * 0.125f) : 0.f)
                   + ((w1 >> (sh + 1)) & 1 ? __expf(acc[nt][3] * 0.125f) : 0.f);
        }

        if (kb + 3 < NTILE) {
            const uint32_t sn = sb + OFF_ST + (uint32_t)((kb + 3) & 3) * 8192;
            const size_t tb = (size_t)(kb + 3) * BKT * 128;
            cpa16(sn + drow0, khb + tb + srow0);
            cpa16(sn + drow1, khb + tb + srow1);
        }
        CPA_COMMIT();                        // keeps group count aligned
    }
    CPA_WAIT0();
    __syncthreads();

    // ===== prime pass-B rings: commit1 [K0 + V0], commit2 [K1] =====
    {
        const uint32_t st0 = sb + OFF_ST;
        cpa16(st0 + drow0, khb + srow0);            cpa16(st0 + drow1, khb + srow1);
        cpa16(st0 + 8192 + drow0, klb + srow0);     cpa16(st0 + 8192 + drow1, klb + srow1);
        cpa16(st0 + 16384 + drow0, vhb + srow0);    cpa16(st0 + 16384 + drow1, vhb + srow1);
        cpa16(st0 + 24576 + drow0, vlb + srow0);    cpa16(st0 + 24576 + drow1, vlb + srow1);
        CPA_COMMIT();
        const uint32_t st1 = sb + OFF_ST + 32768;
        cpa16(st1 + drow0, khb + 8192 + srow0);         cpa16(st1 + drow1, khb + 8192 + srow1);
        cpa16(st1 + 8192 + drow0, klb + 8192 + srow0);  cpa16(st1 + 8192 + drow1, klb + 8192 + srow1);
        CPA_COMMIT();
    }

    // ===== inter-pass: row sums -> inv (overlapped with ring refill) =====
    esum0 += __shfl_xor_sync(0xffffffffu, esum0, 1);
    esum0 += __shfl_xor_sync(0xffffffffu, esum0, 2);
    esum1 += __shfl_xor_sync(0xffffffffu, esum1, 1);
    esum1 += __shfl_xor_sync(0xffffffffu, esum1, 2);
    float* rsum = (float*)(sm + OFF_RS);
    float* inv_s = (float*)(sm + OFF_INV);
    if ((lane & 3) == 0) {
        rsum[nhalf * 64 + r0l] = esum0;
        rsum[nhalf * 64 + r0l + 8] = esum1;
    }
    __syncthreads();
    if (tid < 64) inv_s[tid] = 1.f / (rsum[tid] + rsum[64 + tid]);
    __syncthreads();
    const float inv0 = inv_s[r0l], inv1 = inv_s[r0l + 8];

    float Oacc[8][4];
    #pragma unroll
    for (int i = 0; i < 8; ++i)
        #pragma unroll
        for (int c = 0; c < 4; ++c) Oacc[i][c] = 0.f;

    uint32_t Eh[2][4], El[2][4];   // Ê fragments of the PREVIOUS tile

    // ===== PASS B: GEMM1(t) + GEMM2(t-1) back-to-back, then epilogue(t) =====
    for (int kb = 0; kb < NTILE; ++kb) {
        CPA_WAIT1();
        __syncthreads();
        const uint32_t stK = sb + OFF_ST + (uint32_t)(kb % 3) * 32768;
        const uint32_t stV = sb + OFF_ST + (uint32_t)((kb + 2) % 3) * 32768 + 16384;
        const uint32_t w0 = mb0[kb * 2];
        const uint32_t w1 = mb1[kb * 2];

        // ---- GEMM1(kb): full 3-term scores
        float acc[4][4];
        #pragma unroll
        for (int i = 0; i < 4; ++i)
            #pragma unroll
            for (int c = 0; c < 4; ++c) acc[i][c] = 0.f;

        #pragma unroll
        for (int ks = 0; ks < 4; ++ks) {
            #pragma unroll
            for (int np = 0; np < 2; ++np) {
                uint32_t bh4[4], bl4[4];
                const uint32_t bo = nbase + (uint32_t)np * 2048 +
                                    ((ncol0 + (uint32_t)ks * 32) ^ nxor);
                ldsm4(stK + bo, bh4);
                ldsm4(stK + 8192 + bo, bl4);
                mma_bf16(acc[np * 2], qah[ks], bh4[0], bh4[1]);
                mma_bf16(acc[np * 2], qah[ks], bl4[0], bl4[1]);
                mma_bf16(acc[np * 2], qal[ks], bh4[0], bh4[1]);
                mma_bf16(acc[np * 2 + 1], qah[ks], bh4[2], bh4[3]);
                mma_bf16(acc[np * 2 + 1], qah[ks], bl4[2], bl4[3]);
                mma_bf16(acc[np * 2 + 1], qal[ks], bh4[2], bh4[3]);
            }
        }

        // ---- GEMM2(kb-1): O += Ê(kb-1) . V(kb-1)   (contiguous with GEMM1)
        if (kb) {
            #pragma unroll
            for (int kk = 0; kk < 2; ++kk) {
                const uint32_t vrt = vbase_off + (uint32_t)kk * 2048;
                #pragma unroll
                for (int dt2 = 0; dt2 < 4; ++dt2) {
                    uint32_t vh4[4], vl4[4];
                    const uint32_t o = vrt + ((vcol0 + (uint32_t)dt2 * 32) ^ vxor);
                    ldsm4t(stV + o, vh4);
                    ldsm4t(stV + 8192 + o, vl4);
                    mma_bf16(Oacc[dt2 * 2], Eh[kk], vh4[0], vh4[1]);
                    mma_bf16(Oacc[dt2 * 2], Eh[kk], vl4[0], vl4[1]);
                    mma_bf16(Oacc[dt2 * 2], El[kk], vh4[0], vh4[1]);
                    mma_bf16(Oacc[dt2 * 2 + 1], Eh[kk], vh4[2], vh4[3]);
                    mma_bf16(Oacc[dt2 * 2 + 1], Eh[kk], vl4[2], vl4[3]);
                    mma_bf16(Oacc[dt2 * 2 + 1], El[kk], vh4[2], vh4[3]);
                }
            }
        }

        // ---- epilogue(kb): ê = exp * inv, p write, pack into Eh/El (now free)
        const int cb = kb * BKT + nhalf * 32 + coff;
        float* prow0 = p + ((size_t)(bh * S_LEN) + q0 + r0l) * S_LEN + cb;
        float* prow1 = prow0 + (size_t)8 * S_LEN;
        #pragma unroll
        for (int nt = 0; nt < 4; ++nt) {
            const int sh = coff + nt * 8;
            float e0 = (w0 >> sh) & 1 ? __expf(acc[nt][0] * 0.125f) * inv0 : 0.f;
            float e1 = (w0 >> (sh + 1)) & 1 ? __expf(acc[nt][1] * 0.125f) * inv0 : 0.f;
            float e2 = (w1 >> sh) & 1 ? __expf(acc[nt][2] * 0.125f) * inv1 : 0.f;
            float e3 = (w1 >> (sh + 1)) & 1 ? __expf(acc[nt][3] * 0.125f) * inv1 : 0.f;
            *(float2*)(prow0 + nt * 8) = make_float2(e0, e1);
            *(float2*)(prow1 + nt * 8) = make_float2(e2, e3);
            uint32_t u01 = pk2(e0, e1), u23 = pk2(e2, e3);
            const int kk = nt >> 1, sl = (nt & 1) * 2;
            Eh[kk][sl + 0] = u01;
            Eh[kk][sl + 1] = u23;
            El[kk][sl + 0] = pk2(e0 - lo16f(u01), e1 - hi16f(u01));
            El[kk][sl + 1] = pk2(e2 - lo16f(u23), e3 - hi16f(u23));
        }

        // ---- refill: K(kb+2) into slot (kb+2)%3, V(kb+1) into slot (kb+1)%3
        if (kb + 2 < NTILE) {
            const uint32_t sn = sb + OFF_ST + (uint32_t)((kb + 2) % 3) * 32768;
            const size_t tb = (size_t)(kb + 2) * BKT * 128;
            cpa16(sn + drow0, khb + tb + srow0);          cpa16(sn + drow1, khb + tb + srow1);
            cpa16(sn + 8192 + drow0, klb + tb + srow0);   cpa16(sn + 8192 + drow1, klb + tb + srow1);
        }
        if (kb + 1 < NTILE) {
            const uint32_t sv = sb + OFF_ST + (uint32_t)((kb + 1) % 3) * 32768 + 16384;
            const size_t tb = (size_t)(kb + 1) * BKT * 128;
            cpa16(sv + drow0, vhb + tb + srow0);          cpa16(sv + drow1, vhb + tb + srow1);
            cpa16(sv + 8192 + drow0, vlb + tb + srow0);   cpa16(sv + 8192 + drow1, vlb + tb + srow1);
        }
        CPA_COMMIT();
    }

    // ---- tail: GEMM2 for the last tile (V(NTILE-1) slot untouched since load)
    {
        const uint32_t stV = sb + OFF_ST + (uint32_t)((NTILE - 1) % 3) * 32768 + 16384;
        #pragma unroll
        for (int kk = 0; kk < 2; ++kk) {
            const uint32_t vrt = vbase_off + (uint32_t)kk * 2048;
            #pragma unroll
            for (int dt2 = 0; dt2 < 4; ++dt2) {
                uint32_t vh4[4], vl4[4];
                const uint32_t o = vrt + ((vcol0 + (uint32_t)dt2 * 32) ^ vxor);
                ldsm4t(stV + o, vh4);
                ldsm4t(stV + 8192 + o, vl4);
                mma_bf16(Oacc[dt2 * 2], Eh[kk], vh4[0], vh4[1]);
                mma_bf16(Oacc[dt2 * 2], Eh[kk], vl4[0], vl4[1]);
                mma_bf16(Oacc[dt2 * 2], El[kk], vh4[0], vh4[1]);
                mma_bf16(Oacc[dt2 * 2 + 1], Eh[kk], vh4[2], vh4[3]);
                mma_bf16(Oacc[dt2 * 2 + 1], Eh[kk], vl4[2], vl4[3]);
                mma_bf16(Oacc[dt2 * 2 + 1], El[kk], vh4[2], vh4[3]);
            }
        }
    }
    CPA_WAIT0();
    __syncthreads();      // all ring reads done; smem reusable

    // ---- O combine across nhalf halves (already normalized) and store
    float* Osm = (float*)(sm + OFF_OSM);
    if (nhalf == 1) {
        #pragma unroll
        for (int dt = 0; dt < 8; ++dt) {
            *(float2*)&Osm[r0l * 64 + dt * 8 + coff] = make_float2(Oacc[dt][0], Oacc[dt][1]);
            *(float2*)&Osm[(r0l + 8) * 64 + dt * 8 + coff] = make_float2(Oacc[dt][2], Oacc[dt][3]);
        }
    }
    __syncthreads();
    if (nhalf == 0) {
        float* orow0 = out + ((size_t)(bh * S_LEN) + q0 + r0l) * DH + coff;
        float* orow1 = orow0 + 8 * DH;
        #pragma unroll
        for (int dt = 0; dt < 8; ++dt) {
            float2 a0 = *(float2*)&Osm[r0l * 64 + dt * 8 + coff];
            float2 a1 = *(float2*)&Osm[(r0l + 8) * 64 + dt * 8 + coff];
            *(float2*)(orow0 + dt * 8) = make_float2(Oacc[dt][0] + a0.x, Oacc[dt][1] + a0.y);
            *(float2*)(orow1 + dt * 8) = make_float2(Oacc[dt][2] + a1.x, Oacc[dt][3] + a1.y);
        }
    }
}

extern "C" void kernel_launch(void* const* d_in, const int* in_sizes, int n_in,
                              void* d_out, int out_size)
{
    const float* q    = (const float*)d_in[0];
    const float* k    = (const float*)d_in[1];
    const float* v    = (const float*)d_in[2];
    const int*   mask = (const int*)d_in[3];

    float* out = (float*)d_out;
    float* p   = out + NELEM;

    uint2 *qhi, *qlo, *khi, *klo, *vhi, *vlo;
    uint32_t* mbits;
    cudaGetSymbolAddress((void**)&qhi, g_qhi);
    cudaGetSymbolAddress((void**)&qlo, g_qlo);
    cudaGetSymbolAddress((void**)&khi, g_khi);
    cudaGetSymbolAddress((void**)&klo, g_klo);
    cudaGetSymbolAddress((void**)&vhi, g_vhi);
    cudaGetSymbolAddress((void**)&vlo, g_vlo);
    cudaGetSymbolAddress((void**)&mbits, g_mbits);

    const unsigned gpre = (unsigned)(NELEM / 4 / 256);
    presplit<<<gpre, 256>>>((const float4*)q, qhi, qlo);
    presplit<<<gpre, 256>>>((const float4*)k, khi, klo);
    presplit<<<gpre, 256>>>((const float4*)v, vhi, vlo);
    pmask<<<(unsigned)((size_t)S_LEN * (S_LEN / 32) / 256), 256>>>(mask, mbits);

    cudaFuncSetAttribute(attn_mma, cudaFuncAttributeMaxDynamicSharedMemorySize, SMEM_SZ);
    dim3 g1(S_LEN / BQ, BHN);
    attn_mma<<<g1, 256, SMEM_SZ>>>(out, p);
}

// round 13
// speedup vs baseline: 1.8630x; 1.8630x over previous
#include <cuda_runtime.h>
#include <cuda_fp16.h>
#include <cstdint>

// Problem constants: B=4, H=16, S=2048, D=64
#define S_LEN 2048
#define DH    64
#define BHN   64
#define BQ    64            // query rows per CTA
#define BKT   64            // key rows per tile
#define NTILE 32
#define NELEM ((size_t)BHN * S_LEN * DH)   // 8388608

// smem: Q hi [64x64] + ring region
//  pass A: 4 stages x 8KB (KH only)
//  pass B: 3 stages x 32KB {KH,KL,VH,VL}
#define OFF_QH 0
#define OFF_ST 16384
#define SMEM_SZ (16384 + 3 * 32768)   // 114688
// post-hoist reuse of the (dead) Q region
#define OFF_RS  0           // float rsum[2][64]
#define OFF_INV 512         // float inv_s[64]
#define OFF_OSM 16384       // float Osm[64][64] (tail only)

typedef unsigned long long ull;

// pre-split fp16 hi/lo copies of q,k,v + bit-packed mask (q lo unused)
__device__ __align__(16) uint2 g_qhi[NELEM / 4], g_qlo[NELEM / 4];
__device__ __align__(16) uint2 g_khi[NELEM / 4], g_klo[NELEM / 4];
__device__ __align__(16) uint2 g_vhi[NELEM / 4], g_vlo[NELEM / 4];
__device__ uint32_t g_mbits[(size_t)S_LEN * (S_LEN / 32)];   // [row][word]

// ---------------- helpers ----------------
__device__ __forceinline__ uint32_t s2u(const void* p) {
    uint32_t a;
    asm("{ .reg .u64 t; cvta.to.shared.u64 t, %1; cvt.u32.u64 %0, t; }" : "=r"(a) : "l"(p));
    return a;
}
__device__ __forceinline__ void ldsm4(uint32_t a, uint32_t* r) {
    asm volatile("ldmatrix.sync.aligned.m8n8.x4.shared.b16 {%0,%1,%2,%3}, [%4];"
                 : "=r"(r[0]), "=r"(r[1]), "=r"(r[2]), "=r"(r[3]) : "r"(a));
}
__device__ __forceinline__ void ldsm4t(uint32_t a, uint32_t* r) {
    asm volatile("ldmatrix.sync.aligned.m8n8.x4.trans.shared.b16 {%0,%1,%2,%3}, [%4];"
                 : "=r"(r[0]), "=r"(r[1]), "=r"(r[2]), "=r"(r[3]) : "r"(a));
}
__device__ __forceinline__ void mma_f16(float* d, const uint32_t* a,
                                        uint32_t b0, uint32_t b1) {
    asm volatile("mma.sync.aligned.m16n8k16.row.col.f32.f16.f16.f32 "
                 "{%0,%1,%2,%3},{%4,%5,%6,%7},{%8,%9},{%0,%1,%2,%3};"
                 : "+f"(d[0]), "+f"(d[1]), "+f"(d[2]), "+f"(d[3])
                 : "r"(a[0]), "r"(a[1]), "r"(a[2]), "r"(a[3]), "r"(b0), "r"(b1));
}
// pack two f32 -> f16x2 (lo in low half / element 0)
__device__ __forceinline__ uint32_t pk2(float lo, float hi) {
    uint32_t r;
    asm("cvt.rn.f16x2.f32 %0, %1, %2;" : "=r"(r) : "f"(hi), "f"(lo));
    return r;
}
__device__ __forceinline__ float lo16f(uint32_t u) {
    float f;
    asm("{ .reg .b16 h, j; mov.b32 {h, j}, %1; cvt.f32.f16 %0, h; }" : "=f"(f) : "r"(u));
    return f;
}
__device__ __forceinline__ float hi16f(uint32_t u) {
    float f;
    asm("{ .reg .b16 h, j; mov.b32 {h, j}, %1; cvt.f32.f16 %0, j; }" : "=f"(f) : "r"(u));
    return f;
}

__device__ __forceinline__ void cpa16(uint32_t dst, const void* src) {
    asm volatile("cp.async.cg.shared.global [%0], [%1], 16;" :: "r"(dst), "l"(src));
}
#define CPA_COMMIT() asm volatile("cp.async.commit_group;" ::: "memory")
#define CPA_WAIT2()  asm volatile("cp.async.wait_group 2;" ::: "memory")
#define CPA_WAIT1()  asm volatile("cp.async.wait_group 1;" ::: "memory")
#define CPA_WAIT0()  asm volatile("cp.async.wait_group 0;" ::: "memory")

// ---------------- pre-pass kernels ----------------
__global__ __launch_bounds__(256) void presplit(const float4* __restrict__ src,
                                                uint2* __restrict__ dhi,
                                                uint2* __restrict__ dlo)
{
    int i = blockIdx.x * blockDim.x + threadIdx.x;
    float4 t = src[i];
    uint32_t h01 = pk2(t.x, t.y), h23 = pk2(t.z, t.w);
    uint32_t l01 = pk2(t.x - lo16f(h01), t.y - hi16f(h01));
    uint32_t l23 = pk2(t.z - lo16f(h23), t.w - hi16f(h23));
    dhi[i] = make_uint2(h01, h23);
    dlo[i] = make_uint2(l01, l23);
}

__global__ __launch_bounds__(256) void pmask(const int* __restrict__ mask,
                                             uint32_t* __restrict__ bits)
{
    int idx = blockIdx.x * blockDim.x + threadIdx.x;   // word index
    const int4* m4 = (const int4*)mask + (size_t)idx * 8;
    uint32_t b = 0;
    #pragma unroll
    for (int i = 0; i < 8; ++i) {
        int4 v = m4[i];
        b |= (v.x != 0 ? 1u : 0u) << (i * 4);
        b |= (v.y != 0 ? 1u : 0u) << (i * 4 + 1);
        b |= (v.z != 0 ? 1u : 0u) << (i * 4 + 2);
        b |= (v.w != 0 ? 1u : 0u) << (i * 4 + 3);
    }
    bits[idx] = b;
}

__global__ __launch_bounds__(256, 2)
void attn_mma(float* __restrict__ out, float* __restrict__ p)
{
    extern __shared__ char sm[];
    const uint32_t sb = s2u(sm);
    const int tid = threadIdx.x;
    const int wid = tid >> 5, lane = tid & 31;
    const int rg = wid >> 1;                 // row group (16 rows)
    const int nhalf = wid & 1;               // 32-col half of tile
    const int bh = blockIdx.y;
    const int q0 = blockIdx.x * BQ;

    // cp.async mapping: chunk cc (16B), rows rr, rr+32
    const int cc = tid & 7, rr = tid >> 3;
    const uint32_t dcol = ((uint32_t)cc) << 4;
    const uint32_t drow0 = (uint32_t)rr * 128 + (dcol ^ (((uint32_t)rr & 7) << 4));
    const uint32_t drow1 = (uint32_t)(rr + 32) * 128 + (dcol ^ ((((uint32_t)rr + 32) & 7) << 4));
    const size_t srow0 = (size_t)rr * 128 + cc * 16;
    const size_t srow1 = (size_t)(rr + 32) * 128 + cc * 16;

    const char* khb = (const char*)g_khi + (size_t)bh * S_LEN * 128;
    const char* klb = (const char*)g_klo + (size_t)bh * S_LEN * 128;
    const char* vhb = (const char*)g_vhi + (size_t)bh * S_LEN * 128;
    const char* vlb = (const char*)g_vlo + (size_t)bh * S_LEN * 128;

    // epilogue thread mapping (m16n8 accum layout)
    const int r0l = rg * 16 + (lane >> 2);
    const int coff = (lane & 3) * 2;

    // ldmatrix lane mappings (XOR applied AFTER column adds)
    const int arow = rg * 16 + (lane & 15);
    const uint32_t arowoff = (uint32_t)arow * 128;
    const uint32_t acol0 = ((uint32_t)(lane >> 4)) << 4;
    const uint32_t axor = ((uint32_t)arow & 7) << 4;
    const int nrow = ((lane >> 4) << 3) + (lane & 7);
    const uint32_t nbase = (uint32_t)(nhalf * 32 + nrow) * 128;
    const uint32_t ncol0 = (((uint32_t)lane >> 3) & 1) << 4;
    const uint32_t nxor = ((uint32_t)(nrow & 7)) << 4;
    const int vrow = (((lane >> 3) & 1) << 3) + (lane & 7);
    const uint32_t vbase_off = (uint32_t)(nhalf * 32 + vrow) * 128;
    const uint32_t vcol0 = ((uint32_t)(lane >> 4)) << 4;
    const uint32_t vxor = ((uint32_t)(vrow & 7)) << 4;

    const uint32_t* mb0 = g_mbits + (size_t)(q0 + r0l) * 64 + nhalf;
    const uint32_t* mb1 = mb0 + 8 * 64;

    // ===== prologue: Q(hi only) + pass-A 4-stage KH ring prime =====
    {
        const char* qh = (const char*)g_qhi + ((size_t)bh * S_LEN + q0) * 128;
        cpa16(sb + OFF_QH + drow0, qh + srow0);
        cpa16(sb + OFF_QH + drow1, qh + srow1);
        cpa16(sb + OFF_ST + drow0, khb + srow0);
        cpa16(sb + OFF_ST + drow1, khb + srow1);
        CPA_COMMIT();
        #pragma unroll
        for (int s = 1; s < 3; ++s) {
            const uint32_t st = sb + OFF_ST + (uint32_t)s * 8192;
            const size_t tb = (size_t)s * BKT * 128;
            cpa16(st + drow0, khb + tb + srow0);
            cpa16(st + drow1, khb + tb + srow1);
            CPA_COMMIT();
        }
    }
    CPA_WAIT2();          // Q + stage0 complete
    __syncthreads();

    // ---- hoist Q hi fragments (tile-invariant) into registers
    uint32_t qah[4][4];
    #pragma unroll
    for (int ks = 0; ks < 4; ++ks) {
        const uint32_t ao = arowoff + ((acol0 + (uint32_t)ks * 32) ^ axor);
        ldsm4(sb + OFF_QH + ao, qah[ks]);
    }

    float esum0 = 0.f, esum1 = 0.f;

    // ===== PASS A: approximate row sums (Qh.Kh fp16; ~5e-5 rel err on l) =====
    for (int kb = 0; kb < NTILE; ++kb) {
        if (kb) { CPA_WAIT2(); __syncthreads(); }
        const uint32_t st = sb + OFF_ST + (uint32_t)(kb & 3) * 8192;
        const uint32_t w0 = mb0[kb * 2];
        const uint32_t w1 = mb1[kb * 2];

        float acc[4][4];
        #pragma unroll
        for (int i = 0; i < 4; ++i)
            #pragma unroll
            for (int c = 0; c < 4; ++c) acc[i][c] = 0.f;

        #pragma unroll
        for (int ks = 0; ks < 4; ++ks) {
            #pragma unroll
            for (int np = 0; np < 2; ++np) {
                uint32_t bh4[4];
                const uint32_t bo = nbase + (uint32_t)np * 2048 +
                                    ((ncol0 + (uint32_t)ks * 32) ^ nxor);
                ldsm4(st + bo, bh4);
                mma_f16(acc[np * 2], qah[ks], bh4[0], bh4[1]);
                mma_f16(acc[np * 2 + 1], qah[ks], bh4[2], bh4[3]);
            }
        }

        #pragma unroll
        for (int nt = 0; nt < 4; ++nt) {
            const int sh = coff + nt * 8;
            esum0 += ((w0 >> sh) & 1 ? __expf(acc[nt][0] * 0.125f) : 0.f)
                   + ((w0 >> (sh + 1)) & 1 ? __expf(acc[nt][1] * 0.125f) : 0.f);
            esum1 += ((w1 >> sh) & 1 ? __expf(acc[nt][2] * 0.125f) : 0.f)
                   + ((w1 >> (sh + 1)) & 1 ? __expf(acc[nt][3] * 0.125f) : 0.f);
        }

        if (kb + 3 < NTILE) {
            const uint32_t sn = sb + OFF_ST + (uint32_t)((kb + 3) & 3) * 8192;
            const size_t tb = (size_t)(kb + 3) * BKT * 128;
            cpa16(sn + drow0, khb + tb + srow0);
            cpa16(sn + drow1, khb + tb + srow1);
        }
        CPA_COMMIT();                        // keeps group count aligned
    }
    CPA_WAIT0();
    __syncthreads();

    // ===== prime pass-B ring (K + V), overlapped with inter-pass reduction =====
    {
        #pragma unroll
        for (int s = 0; s < 2; ++s) {
            const uint32_t st = sb + OFF_ST + (uint32_t)s * 32768;
            const size_t tb = (size_t)s * BKT * 128;
            cpa16(st + drow0, khb + tb + srow0);          cpa16(st + drow1, khb + tb + srow1);
            cpa16(st + 8192 + drow0, klb + tb + srow0);   cpa16(st + 8192 + drow1, klb + tb + srow1);
            cpa16(st + 16384 + drow0, vhb + tb + srow0);  cpa16(st + 16384 + drow1, vhb + tb + srow1);
            cpa16(st + 24576 + drow0, vlb + tb + srow0);  cpa16(st + 24576 + drow1, vlb + tb + srow1);
            CPA_COMMIT();
        }
    }

    // ===== inter-pass: row sums -> inv =====
    esum0 += __shfl_xor_sync(0xffffffffu, esum0, 1);
    esum0 += __shfl_xor_sync(0xffffffffu, esum0, 2);
    esum1 += __shfl_xor_sync(0xffffffffu, esum1, 1);
    esum1 += __shfl_xor_sync(0xffffffffu, esum1, 2);
    float* rsum = (float*)(sm + OFF_RS);
    float* inv_s = (float*)(sm + OFF_INV);
    if ((lane & 3) == 0) {
        rsum[nhalf * 64 + r0l] = esum0;
        rsum[nhalf * 64 + r0l + 8] = esum1;
    }
    __syncthreads();
    if (tid < 64) inv_s[tid] = 1.f / (rsum[tid] + rsum[64 + tid]);
    __syncthreads();
    const float inv0 = inv_s[r0l], inv1 = inv_s[r0l + 8];

    float Oacc[8][4];
    #pragma unroll
    for (int i = 0; i < 8; ++i)
        #pragma unroll
        for (int c = 0; c < 4; ++c) Oacc[i][c] = 0.f;

    // ===== PASS B: 2-product scores, normalized p write + O accumulate =====
    for (int kb = 0; kb < NTILE; ++kb) {
        CPA_WAIT1();
        __syncthreads();
        const uint32_t st = sb + OFF_ST + (uint32_t)(kb % 3) * 32768;
        const uint32_t w0 = mb0[kb * 2];
        const uint32_t w1 = mb1[kb * 2];

        float acc[4][4];
        #pragma unroll
        for (int i = 0; i < 4; ++i)
            #pragma unroll
            for (int c = 0; c < 4; ++c) acc[i][c] = 0.f;

        // ---- GEMM1: S = Qh.(Kh + Kl)  (2 products, fp16)
        #pragma unroll
        for (int ks = 0; ks < 4; ++ks) {
            #pragma unroll
            for (int np = 0; np < 2; ++np) {
                uint32_t bh4[4], bl4[4];
                const uint32_t bo = nbase + (uint32_t)np * 2048 +
                                    ((ncol0 + (uint32_t)ks * 32) ^ nxor);
                ldsm4(st + bo, bh4);
                ldsm4(st + 8192 + bo, bl4);
                mma_f16(acc[np * 2], qah[ks], bh4[0], bh4[1]);
                mma_f16(acc[np * 2], qah[ks], bl4[0], bl4[1]);
                mma_f16(acc[np * 2 + 1], qah[ks], bh4[2], bh4[3]);
                mma_f16(acc[np * 2 + 1], qah[ks], bl4[2], bl4[3]);
            }
        }

        // ---- epilogue: ê = exp * inv (normalized), p write, Êh frags
        uint32_t Eh[2][4];
        const int cb = kb * BKT + nhalf * 32 + coff;
        float* prow0 = p + ((size_t)(bh * S_LEN) + q0 + r0l) * S_LEN + cb;
        float* prow1 = prow0 + (size_t)8 * S_LEN;
        #pragma unroll
        for (int nt = 0; nt < 4; ++nt) {
            const int sh = coff + nt * 8;
            float e0 = (w0 >> sh) & 1 ? __expf(acc[nt][0] * 0.125f) * inv0 : 0.f;
            float e1 = (w0 >> (sh + 1)) & 1 ? __expf(acc[nt][1] * 0.125f) * inv0 : 0.f;
            float e2 = (w1 >> sh) & 1 ? __expf(acc[nt][2] * 0.125f) * inv1 : 0.f;
            float e3 = (w1 >> (sh + 1)) & 1 ? __expf(acc[nt][3] * 0.125f) * inv1 : 0.f;
            *(float2*)(prow0 + nt * 8) = make_float2(e0, e1);
            *(float2*)(prow1 + nt * 8) = make_float2(e2, e3);
            const int kk = nt >> 1, sl = (nt & 1) * 2;
            Eh[kk][sl + 0] = pk2(e0, e1);
            Eh[kk][sl + 1] = pk2(e2, e3);
        }

        // ---- GEMM2: O += Êh.(Vh + Vl)  (2 products, fp16)
        #pragma unroll
        for (int kk = 0; kk < 2; ++kk) {
            const uint32_t vrt = vbase_off + (uint32_t)kk * 2048;
            #pragma unroll
            for (int dt2 = 0; dt2 < 4; ++dt2) {
                uint32_t vh4[4], vl4[4];
                const uint32_t o = vrt + ((vcol0 + (uint32_t)dt2 * 32) ^ vxor);
                ldsm4t(st + 16384 + o, vh4);
                ldsm4t(st + 24576 + o, vl4);
                mma_f16(Oacc[dt2 * 2], Eh[kk], vh4[0], vh4[1]);
                mma_f16(Oacc[dt2 * 2], Eh[kk], vl4[0], vl4[1]);
                mma_f16(Oacc[dt2 * 2 + 1], Eh[kk], vh4[2], vh4[3]);
                mma_f16(Oacc[dt2 * 2 + 1], Eh[kk], vl4[2], vl4[3]);
            }
        }

        if (kb + 2 < NTILE) {
            const uint32_t sn = sb + OFF_ST + (uint32_t)((kb + 2) % 3) * 32768;
            const size_t tb = (size_t)(kb + 2) * BKT * 128;
            cpa16(sn + drow0, khb + tb + srow0);          cpa16(sn + drow1, khb + tb + srow1);
            cpa16(sn + 8192 + drow0, klb + tb + srow0);   cpa16(sn + 8192 + drow1, klb + tb + srow1);
            cpa16(sn + 16384 + drow0, vhb + tb + srow0);  cpa16(sn + 16384 + drow1, vhb + tb + srow1);
            cpa16(sn + 24576 + drow0, vlb + tb + srow0);  cpa16(sn + 24576 + drow1, vlb + tb + srow1);
        }
        CPA_COMMIT();
    }
    CPA_WAIT0();
    __syncthreads();      // ring reads done; smem reusable

    // ---- O combine across nhalf halves (already normalized) and store
    float* Osm = (float*)(sm + OFF_OSM);
    if (nhalf == 1) {
        #pragma unroll
        for (int dt = 0; dt < 8; ++dt) {
            *(float2*)&Osm[r0l * 64 + dt * 8 + coff] = make_float2(Oacc[dt][0], Oacc[dt][1]);
            *(float2*)&Osm[(r0l + 8) * 64 + dt * 8 + coff] = make_float2(Oacc[dt][2], Oacc[dt][3]);
        }
    }
    __syncthreads();
    if (nhalf == 0) {
        float* orow0 = out + ((size_t)(bh * S_LEN) + q0 + r0l) * DH + coff;
        float* orow1 = orow0 + 8 * DH;
        #pragma unroll
        for (int dt = 0; dt < 8; ++dt) {
            float2 a0 = *(float2*)&Osm[r0l * 64 + dt * 8 + coff];
            float2 a1 = *(float2*)&Osm[(r0l + 8) * 64 + dt * 8 + coff];
            *(float2*)(orow0 + dt * 8) = make_float2(Oacc[dt][0] + a0.x, Oacc[dt][1] + a0.y);
            *(float2*)(orow1 + dt * 8) = make_float2(Oacc[dt][2] + a1.x, Oacc[dt][3] + a1.y);
        }
    }
}

extern "C" void kernel_launch(void* const* d_in, const int* in_sizes, int n_in,
                              void* d_out, int out_size)
{
    const float* q    = (const float*)d_in[0];
    const float* k    = (const float*)d_in[1];
    const float* v    = (const float*)d_in[2];
    const int*   mask = (const int*)d_in[3];

    float* out = (float*)d_out;
    float* p   = out + NELEM;

    uint2 *qhi, *qlo, *khi, *klo, *vhi, *vlo;
    uint32_t* mbits;
    cudaGetSymbolAddress((void**)&qhi, g_qhi);
    cudaGetSymbolAddress((void**)&qlo, g_qlo);
    cudaGetSymbolAddress((void**)&khi, g_khi);
    cudaGetSymbolAddress((void**)&klo, g_klo);
    cudaGetSymbolAddress((void**)&vhi, g_vhi);
    cudaGetSymbolAddress((void**)&vlo, g_vlo);
    cudaGetSymbolAddress((void**)&mbits, g_mbits);

    const unsigned gpre = (unsigned)(NELEM / 4 / 256);
    presplit<<<gpre, 256>>>((const float4*)q, qhi, qlo);
    presplit<<<gpre, 256>>>((const float4*)k, khi, klo);
    presplit<<<gpre, 256>>>((const float4*)v, vhi, vlo);
    pmask<<<(unsigned)((size_t)S_LEN * (S_LEN / 32) / 256), 256>>>(mask, mbits);

    cudaFuncSetAttribute(attn_mma, cudaFuncAttributeMaxDynamicSharedMemorySize, SMEM_SZ);
    dim3 g1(S_LEN / BQ, BHN);
    attn_mma<<<g1, 256, SMEM_SZ>>>(out, p);
}

// round 14
// speedup vs baseline: 2.2431x; 1.2040x over previous
#include <cuda_runtime.h>
#include <cuda_fp16.h>
#include <cstdint>

// Problem constants: B=4, H=16, S=2048, D=64
#define S_LEN 2048
#define DH    64
#define BHN   64
#define BQ    64            // query rows per CTA
#define BKT   64            // key rows per tile
#define NTILE 32
#define NELEM ((size_t)BHN * S_LEN * DH)   // 8388608

// smem: Q hi/lo [64x64] fp16 + ring region
//  pass A: 4 stages x 8KB (KH only)
//  pass B: 3 slots x 16KB {KH at +0, VH at +8192}
#define OFF_QH 0
#define OFF_QL 8192
#define OFF_ST 16384
#define SMEM_SZ (16384 + 3 * 16384)   // 65536
// post-loop reuse
#define OFF_RS  0           // float rsum[2][64]
#define OFF_INV 512         // float inv_s[64]
#define OFF_OSM 16384       // float Osm[64][64] (tail only)

typedef unsigned long long ull;

// pre-split fp16 copies: Q hi+lo; K,V hi only. + bit-packed mask
__device__ __align__(16) uint2 g_qhi[NELEM / 4], g_qlo[NELEM / 4];
__device__ __align__(16) uint2 g_khi[NELEM / 4];
__device__ __align__(16) uint2 g_vhi[NELEM / 4];
__device__ uint32_t g_mbits[(size_t)S_LEN * (S_LEN / 32)];   // [row][word]

// ---------------- helpers ----------------
__device__ __forceinline__ uint32_t s2u(const void* p) {
    uint32_t a;
    asm("{ .reg .u64 t; cvta.to.shared.u64 t, %1; cvt.u32.u64 %0, t; }" : "=r"(a) : "l"(p));
    return a;
}
__device__ __forceinline__ void ldsm4(uint32_t a, uint32_t* r) {
    asm volatile("ldmatrix.sync.aligned.m8n8.x4.shared.b16 {%0,%1,%2,%3}, [%4];"
                 : "=r"(r[0]), "=r"(r[1]), "=r"(r[2]), "=r"(r[3]) : "r"(a));
}
__device__ __forceinline__ void ldsm4t(uint32_t a, uint32_t* r) {
    asm volatile("ldmatrix.sync.aligned.m8n8.x4.trans.shared.b16 {%0,%1,%2,%3}, [%4];"
                 : "=r"(r[0]), "=r"(r[1]), "=r"(r[2]), "=r"(r[3]) : "r"(a));
}
__device__ __forceinline__ void mma_f16(float* d, const uint32_t* a,
                                        uint32_t b0, uint32_t b1) {
    asm volatile("mma.sync.aligned.m16n8k16.row.col.f32.f16.f16.f32 "
                 "{%0,%1,%2,%3},{%4,%5,%6,%7},{%8,%9},{%0,%1,%2,%3};"
                 : "+f"(d[0]), "+f"(d[1]), "+f"(d[2]), "+f"(d[3])
                 : "r"(a[0]), "r"(a[1]), "r"(a[2]), "r"(a[3]), "r"(b0), "r"(b1));
}
// pack two f32 -> f16x2 (lo in low half / element 0)
__device__ __forceinline__ uint32_t pk2(float lo, float hi) {
    uint32_t r;
    asm("cvt.rn.f16x2.f32 %0, %1, %2;" : "=r"(r) : "f"(hi), "f"(lo));
    return r;
}
__device__ __forceinline__ float lo16f(uint32_t u) {
    float f;
    asm("{ .reg .b16 h, j; mov.b32 {h, j}, %1; cvt.f32.f16 %0, h; }" : "=f"(f) : "r"(u));
    return f;
}
__device__ __forceinline__ float hi16f(uint32_t u) {
    float f;
    asm("{ .reg .b16 h, j; mov.b32 {h, j}, %1; cvt.f32.f16 %0, j; }" : "=f"(f) : "r"(u));
    return f;
}

__device__ __forceinline__ void cpa16(uint32_t dst, const void* src) {
    asm volatile("cp.async.cg.shared.global [%0], [%1], 16;" :: "r"(dst), "l"(src));
}
#define CPA_COMMIT() asm volatile("cp.async.commit_group;" ::: "memory")
#define CPA_WAIT2()  asm volatile("cp.async.wait_group 2;" ::: "memory")
#define CPA_WAIT1()  asm volatile("cp.async.wait_group 1;" ::: "memory")
#define CPA_WAIT0()  asm volatile("cp.async.wait_group 0;" ::: "memory")

// ---------------- pre-pass kernels ----------------
__global__ __launch_bounds__(256) void presplit(const float4* __restrict__ src,
                                                uint2* __restrict__ dhi,
                                                uint2* __restrict__ dlo)
{
    int i = blockIdx.x * blockDim.x + threadIdx.x;
    float4 t = src[i];
    uint32_t h01 = pk2(t.x, t.y), h23 = pk2(t.z, t.w);
    uint32_t l01 = pk2(t.x - lo16f(h01), t.y - hi16f(h01));
    uint32_t l23 = pk2(t.z - lo16f(h23), t.w - hi16f(h23));
    dhi[i] = make_uint2(h01, h23);
    dlo[i] = make_uint2(l01, l23);
}

__global__ __launch_bounds__(256) void presplit_hi(const float4* __restrict__ src,
                                                   uint2* __restrict__ dhi)
{
    int i = blockIdx.x * blockDim.x + threadIdx.x;
    float4 t = src[i];
    dhi[i] = make_uint2(pk2(t.x, t.y), pk2(t.z, t.w));
}

__global__ __launch_bounds__(256) void pmask(const int* __restrict__ mask,
                                             uint32_t* __restrict__ bits)
{
    int idx = blockIdx.x * blockDim.x + threadIdx.x;   // word index
    const int4* m4 = (const int4*)mask + (size_t)idx * 8;
    uint32_t b = 0;
    #pragma unroll
    for (int i = 0; i < 8; ++i) {
        int4 v = m4[i];
        b |= (v.x != 0 ? 1u : 0u) << (i * 4);
        b |= (v.y != 0 ? 1u : 0u) << (i * 4 + 1);
        b |= (v.z != 0 ? 1u : 0u) << (i * 4 + 2);
        b |= (v.w != 0 ? 1u : 0u) << (i * 4 + 3);
    }
    bits[idx] = b;
}

__global__ __launch_bounds__(256, 2)
void attn_mma(float* __restrict__ out, float* __restrict__ p)
{
    extern __shared__ char sm[];
    const uint32_t sb = s2u(sm);
    const int tid = threadIdx.x;
    const int wid = tid >> 5, lane = tid & 31;
    const int rg = wid >> 1;                 // row group (16 rows)
    const int nhalf = wid & 1;               // 32-col half of tile
    const int bh = blockIdx.y;
    const int q0 = blockIdx.x * BQ;

    // cp.async mapping: chunk cc (16B), rows rr, rr+32
    const int cc = tid & 7, rr = tid >> 3;
    const uint32_t dcol = ((uint32_t)cc) << 4;
    const uint32_t drow0 = (uint32_t)rr * 128 + (dcol ^ (((uint32_t)rr & 7) << 4));
    const uint32_t drow1 = (uint32_t)(rr + 32) * 128 + (dcol ^ ((((uint32_t)rr + 32) & 7) << 4));
    const size_t srow0 = (size_t)rr * 128 + cc * 16;
    const size_t srow1 = (size_t)(rr + 32) * 128 + cc * 16;

    const char* khb = (const char*)g_khi + (size_t)bh * S_LEN * 128;
    const char* vhb = (const char*)g_vhi + (size_t)bh * S_LEN * 128;

    // epilogue thread mapping (m16n8 accum layout)
    const int r0l = rg * 16 + (lane >> 2);
    const int coff = (lane & 3) * 2;

    // ldmatrix lane mappings (XOR applied AFTER column adds)
    const int arow = rg * 16 + (lane & 15);
    const uint32_t arowoff = (uint32_t)arow * 128;
    const uint32_t acol0 = ((uint32_t)(lane >> 4)) << 4;
    const uint32_t axor = ((uint32_t)arow & 7) << 4;
    const int nrow = ((lane >> 4) << 3) + (lane & 7);
    const uint32_t nbase = (uint32_t)(nhalf * 32 + nrow) * 128;
    const uint32_t ncol0 = (((uint32_t)lane >> 3) & 1) << 4;
    const uint32_t nxor = ((uint32_t)(nrow & 7)) << 4;
    const int vrow = (((lane >> 3) & 1) << 3) + (lane & 7);
    const uint32_t vbase_off = (uint32_t)(nhalf * 32 + vrow) * 128;
    const uint32_t vcol0 = ((uint32_t)(lane >> 4)) << 4;
    const uint32_t vxor = ((uint32_t)(vrow & 7)) << 4;

    const uint32_t* mb0 = g_mbits + (size_t)(q0 + r0l) * 64 + nhalf;
    const uint32_t* mb1 = mb0 + 8 * 64;

    // ===== prologue: Q hi+lo + pass-A 4-stage KH ring prime =====
    {
        const char* qh = (const char*)g_qhi + ((size_t)bh * S_LEN + q0) * 128;
        const char* ql = (const char*)g_qlo + ((size_t)bh * S_LEN + q0) * 128;
        cpa16(sb + OFF_QH + drow0, qh + srow0);
        cpa16(sb + OFF_QH + drow1, qh + srow1);
        cpa16(sb + OFF_QL + drow0, ql + srow0);
        cpa16(sb + OFF_QL + drow1, ql + srow1);
        cpa16(sb + OFF_ST + drow0, khb + srow0);
        cpa16(sb + OFF_ST + drow1, khb + srow1);
        CPA_COMMIT();
        #pragma unroll
        for (int s = 1; s < 3; ++s) {
            const uint32_t st = sb + OFF_ST + (uint32_t)s * 8192;
            const size_t tb = (size_t)s * BKT * 128;
            cpa16(st + drow0, khb + tb + srow0);
            cpa16(st + drow1, khb + tb + srow1);
            CPA_COMMIT();
        }
    }
    CPA_WAIT2();          // Q + stage0 complete
    __syncthreads();

    // ---- hoist Q hi+lo fragments (tile-invariant) into registers
    uint32_t qah[4][4], qal[4][4];
    #pragma unroll
    for (int ks = 0; ks < 4; ++ks) {
        const uint32_t ao = arowoff + ((acol0 + (uint32_t)ks * 32) ^ axor);
        ldsm4(sb + OFF_QH + ao, qah[ks]);
        ldsm4(sb + OFF_QL + ao, qal[ks]);
    }

    float esum0 = 0.f, esum1 = 0.f;

    // ===== PASS A: approximate row sums (Qh.Kh fp16) =====
    for (int kb = 0; kb < NTILE; ++kb) {
        if (kb) { CPA_WAIT2(); __syncthreads(); }
        const uint32_t st = sb + OFF_ST + (uint32_t)(kb & 3) * 8192;
        const uint32_t w0 = mb0[kb * 2];
        const uint32_t w1 = mb1[kb * 2];

        float acc[4][4];
        #pragma unroll
        for (int i = 0; i < 4; ++i)
            #pragma unroll
            for (int c = 0; c < 4; ++c) acc[i][c] = 0.f;

        #pragma unroll
        for (int ks = 0; ks < 4; ++ks) {
            #pragma unroll
            for (int np = 0; np < 2; ++np) {
                uint32_t bh4[4];
                const uint32_t bo = nbase + (uint32_t)np * 2048 +
                                    ((ncol0 + (uint32_t)ks * 32) ^ nxor);
                ldsm4(st + bo, bh4);
                mma_f16(acc[np * 2], qah[ks], bh4[0], bh4[1]);
                mma_f16(acc[np * 2 + 1], qah[ks], bh4[2], bh4[3]);
            }
        }

        #pragma unroll
        for (int nt = 0; nt < 4; ++nt) {
            const int sh = coff + nt * 8;
            esum0 += ((w0 >> sh) & 1 ? __expf(acc[nt][0] * 0.125f) : 0.f)
                   + ((w0 >> (sh + 1)) & 1 ? __expf(acc[nt][1] * 0.125f) : 0.f);
            esum1 += ((w1 >> sh) & 1 ? __expf(acc[nt][2] * 0.125f) : 0.f)
                   + ((w1 >> (sh + 1)) & 1 ? __expf(acc[nt][3] * 0.125f) : 0.f);
        }

        if (kb + 3 < NTILE) {
            const uint32_t sn = sb + OFF_ST + (uint32_t)((kb + 3) & 3) * 8192;
            const size_t tb = (size_t)(kb + 3) * BKT * 128;
            cpa16(sn + drow0, khb + tb + srow0);
            cpa16(sn + drow1, khb + tb + srow1);
        }
        CPA_COMMIT();                        // keeps group count aligned
    }
    CPA_WAIT0();
    __syncthreads();

    // ===== prime pass-B ring {KH, VH} x2 slots (overlaps reduction) =====
    {
        #pragma unroll
        for (int s = 0; s < 2; ++s) {
            const uint32_t st = sb + OFF_ST + (uint32_t)s * 16384;
            const size_t tb = (size_t)s * BKT * 128;
            cpa16(st + drow0, khb + tb + srow0);          cpa16(st + drow1, khb + tb + srow1);
            cpa16(st + 8192 + drow0, vhb + tb + srow0);   cpa16(st + 8192 + drow1, vhb + tb + srow1);
            CPA_COMMIT();
        }
    }

    // ===== inter-pass: row sums -> inv =====
    esum0 += __shfl_xor_sync(0xffffffffu, esum0, 1);
    esum0 += __shfl_xor_sync(0xffffffffu, esum0, 2);
    esum1 += __shfl_xor_sync(0xffffffffu, esum1, 1);
    esum1 += __shfl_xor_sync(0xffffffffu, esum1, 2);
    float* rsum = (float*)(sm + OFF_RS);
    float* inv_s = (float*)(sm + OFF_INV);
    if ((lane & 3) == 0) {
        rsum[nhalf * 64 + r0l] = esum0;
        rsum[nhalf * 64 + r0l + 8] = esum1;
    }
    __syncthreads();
    if (tid < 64) inv_s[tid] = 1.f / (rsum[tid] + rsum[64 + tid]);
    __syncthreads();
    const float inv0 = inv_s[r0l], inv1 = inv_s[r0l + 8];

    float Oacc[8][4];
    #pragma unroll
    for (int i = 0; i < 8; ++i)
        #pragma unroll
        for (int c = 0; c < 4; ++c) Oacc[i][c] = 0.f;

    // ===== PASS B: S = (Qh+Ql).Kh ; O += Êh.Vh ; normalized p write =====
    for (int kb = 0; kb < NTILE; ++kb) {
        CPA_WAIT1();
        __syncthreads();
        const uint32_t st = sb + OFF_ST + (uint32_t)(kb % 3) * 16384;
        const uint32_t w0 = mb0[kb * 2];
        const uint32_t w1 = mb1[kb * 2];

        float acc[4][4];
        #pragma unroll
        for (int i = 0; i < 4; ++i)
            #pragma unroll
            for (int c = 0; c < 4; ++c) acc[i][c] = 0.f;

        // ---- GEMM1: S = (Qh + Ql).Kh  (2 products, K loaded once)
        #pragma unroll
        for (int ks = 0; ks < 4; ++ks) {
            #pragma unroll
            for (int np = 0; np < 2; ++np) {
                uint32_t bh4[4];
                const uint32_t bo = nbase + (uint32_t)np * 2048 +
                                    ((ncol0 + (uint32_t)ks * 32) ^ nxor);
                ldsm4(st + bo, bh4);
                mma_f16(acc[np * 2], qah[ks], bh4[0], bh4[1]);
                mma_f16(acc[np * 2], qal[ks], bh4[0], bh4[1]);
                mma_f16(acc[np * 2 + 1], qah[ks], bh4[2], bh4[3]);
                mma_f16(acc[np * 2 + 1], qal[ks], bh4[2], bh4[3]);
            }
        }

        // ---- epilogue: ê = exp * inv (normalized), p write, Êh frags
        uint32_t Eh[2][4];
        const int cb = kb * BKT + nhalf * 32 + coff;
        float* prow0 = p + ((size_t)(bh * S_LEN) + q0 + r0l) * S_LEN + cb;
        float* prow1 = prow0 + (size_t)8 * S_LEN;
        #pragma unroll
        for (int nt = 0; nt < 4; ++nt) {
            const int sh = coff + nt * 8;
            float e0 = (w0 >> sh) & 1 ? __expf(acc[nt][0] * 0.125f) * inv0 : 0.f;
            float e1 = (w0 >> (sh + 1)) & 1 ? __expf(acc[nt][1] * 0.125f) * inv0 : 0.f;
            float e2 = (w1 >> sh) & 1 ? __expf(acc[nt][2] * 0.125f) * inv1 : 0.f;
            float e3 = (w1 >> (sh + 1)) & 1 ? __expf(acc[nt][3] * 0.125f) * inv1 : 0.f;
            *(float2*)(prow0 + nt * 8) = make_float2(e0, e1);
            *(float2*)(prow1 + nt * 8) = make_float2(e2, e3);
            const int kk = nt >> 1, sl = (nt & 1) * 2;
            Eh[kk][sl + 0] = pk2(e0, e1);
            Eh[kk][sl + 1] = pk2(e2, e3);
        }

        // ---- GEMM2: O += Êh.Vh  (1 product, V loaded once)
        #pragma unroll
        for (int kk = 0; kk < 2; ++kk) {
            const uint32_t vrt = vbase_off + (uint32_t)kk * 2048;
            #pragma unroll
            for (int dt2 = 0; dt2 < 4; ++dt2) {
                uint32_t vh4[4];
                const uint32_t o = vrt + ((vcol0 + (uint32_t)dt2 * 32) ^ vxor);
                ldsm4t(st + 8192 + o, vh4);
                mma_f16(Oacc[dt2 * 2], Eh[kk], vh4[0], vh4[1]);
                mma_f16(Oacc[dt2 * 2 + 1], Eh[kk], vh4[2], vh4[3]);
            }
        }

        if (kb + 2 < NTILE) {
            const uint32_t sn = sb + OFF_ST + (uint32_t)((kb + 2) % 3) * 16384;
            const size_t tb = (size_t)(kb + 2) * BKT * 128;
            cpa16(sn + drow0, khb + tb + srow0);          cpa16(sn + drow1, khb + tb + srow1);
            cpa16(sn + 8192 + drow0, vhb + tb + srow0);   cpa16(sn + 8192 + drow1, vhb + tb + srow1);
        }
        CPA_COMMIT();
    }
    CPA_WAIT0();
    __syncthreads();      // ring reads done; smem reusable

    // ---- O combine across nhalf halves (already normalized) and store
    float* Osm = (float*)(sm + OFF_OSM);
    if (nhalf == 1) {
        #pragma unroll
        for (int dt = 0; dt < 8; ++dt) {
            *(float2*)&Osm[r0l * 64 + dt * 8 + coff] = make_float2(Oacc[dt][0], Oacc[dt][1]);
            *(float2*)&Osm[(r0l + 8) * 64 + dt * 8 + coff] = make_float2(Oacc[dt][2], Oacc[dt][3]);
        }
    }
    __syncthreads();
    if (nhalf == 0) {
        float* orow0 = out + ((size_t)(bh * S_LEN) + q0 + r0l) * DH + coff;
        float* orow1 = orow0 + 8 * DH;
        #pragma unroll
        for (int dt = 0; dt < 8; ++dt) {
            float2 a0 = *(float2*)&Osm[r0l * 64 + dt * 8 + coff];
            float2 a1 = *(float2*)&Osm[(r0l + 8) * 64 + dt * 8 + coff];
            *(float2*)(orow0 + dt * 8) = make_float2(Oacc[dt][0] + a0.x, Oacc[dt][1] + a0.y);
            *(float2*)(orow1 + dt * 8) = make_float2(Oacc[dt][2] + a1.x, Oacc[dt][3] + a1.y);
        }
    }
}

extern "C" void kernel_launch(void* const* d_in, const int* in_sizes, int n_in,
                              void* d_out, int out_size)
{
    const float* q    = (const float*)d_in[0];
    const float* k    = (const float*)d_in[1];
    const float* v    = (const float*)d_in[2];
    const int*   mask = (const int*)d_in[3];

    float* out = (float*)d_out;
    float* p   = out + NELEM;

    uint2 *qhi, *qlo, *khi, *vhi;
    uint32_t* mbits;
    cudaGetSymbolAddress((void**)&qhi, g_qhi);
    cudaGetSymbolAddress((void**)&qlo, g_qlo);
    cudaGetSymbolAddress((void**)&khi, g_khi);
    cudaGetSymbolAddress((void**)&vhi, g_vhi);
    cudaGetSymbolAddress((void**)&mbits, g_mbits);

    const unsigned gpre = (unsigned)(NELEM / 4 / 256);
    presplit<<<gpre, 256>>>((const float4*)q, qhi, qlo);
    presplit_hi<<<gpre, 256>>>((const float4*)k, khi);
    presplit_hi<<<gpre, 256>>>((const float4*)v, vhi);
    pmask<<<(unsigned)((size_t)S_LEN * (S_LEN / 32) / 256), 256>>>(mask, mbits);

    cudaFuncSetAttribute(attn_mma, cudaFuncAttributeMaxDynamicSharedMemorySize, SMEM_SZ);
    dim3 g1(S_LEN / BQ, BHN);
    attn_mma<<<g1, 256, SMEM_SZ>>>(out, p);
}

// round 15
// speedup vs baseline: 2.2732x; 1.0134x over previous
#include <cuda_runtime.h>
#include <cuda_fp16.h>
#include <cstdint>

// Problem constants: B=4, H=16, S=2048, D=64
#define S_LEN 2048
#define DH    64
#define BHN   64
#define BQ    64            // query rows per CTA
#define BKT   64            // key rows per tile
#define NTILE 32
#define NELEM ((size_t)BHN * S_LEN * DH)   // 8388608

// smem: Q hi [64x64] fp16 + ring region
//  pass A: 4 stages x 8KB (KH only)
//  pass B: 4 slots x 16KB {KH at +0, VH at +8192}
#define OFF_QH 0
#define OFF_ST 8192
#define SMEM_SZ (8192 + 4 * 16384)   // 73728
// post-loop reuse
#define OFF_RS  0           // float rsum[2][64]
#define OFF_INV 512         // float inv_s[64]
#define OFF_OSM 8192        // float Osm[64][64] (tail only)

typedef unsigned long long ull;

// fp16 hi copies of q,k,v + bit-packed mask
__device__ __align__(16) uint2 g_qhi[NELEM / 4];
__device__ __align__(16) uint2 g_khi[NELEM / 4];
__device__ __align__(16) uint2 g_vhi[NELEM / 4];
__device__ uint32_t g_mbits[(size_t)S_LEN * (S_LEN / 32)];   // [row][word]

// ---------------- helpers ----------------
__device__ __forceinline__ uint32_t s2u(const void* p) {
    uint32_t a;
    asm("{ .reg .u64 t; cvta.to.shared.u64 t, %1; cvt.u32.u64 %0, t; }" : "=r"(a) : "l"(p));
    return a;
}
__device__ __forceinline__ void ldsm4(uint32_t a, uint32_t* r) {
    asm volatile("ldmatrix.sync.aligned.m8n8.x4.shared.b16 {%0,%1,%2,%3}, [%4];"
                 : "=r"(r[0]), "=r"(r[1]), "=r"(r[2]), "=r"(r[3]) : "r"(a));
}
__device__ __forceinline__ void ldsm4t(uint32_t a, uint32_t* r) {
    asm volatile("ldmatrix.sync.aligned.m8n8.x4.trans.shared.b16 {%0,%1,%2,%3}, [%4];"
                 : "=r"(r[0]), "=r"(r[1]), "=r"(r[2]), "=r"(r[3]) : "r"(a));
}
__device__ __forceinline__ void mma_f16(float* d, const uint32_t* a,
                                        uint32_t b0, uint32_t b1) {
    asm volatile("mma.sync.aligned.m16n8k16.row.col.f32.f16.f16.f32 "
                 "{%0,%1,%2,%3},{%4,%5,%6,%7},{%8,%9},{%0,%1,%2,%3};"
                 : "+f"(d[0]), "+f"(d[1]), "+f"(d[2]), "+f"(d[3])
                 : "r"(a[0]), "r"(a[1]), "r"(a[2]), "r"(a[3]), "r"(b0), "r"(b1));
}
// pack two f32 -> f16x2 (lo in low half / element 0)
__device__ __forceinline__ uint32_t pk2(float lo, float hi) {
    uint32_t r;
    asm("cvt.rn.f16x2.f32 %0, %1, %2;" : "=r"(r) : "f"(hi), "f"(lo));
    return r;
}

__device__ __forceinline__ void cpa16(uint32_t dst, const void* src) {
    asm volatile("cp.async.cg.shared.global [%0], [%1], 16;" :: "r"(dst), "l"(src));
}
#define CPA_COMMIT() asm volatile("cp.async.commit_group;" ::: "memory")
#define CPA_WAIT2()  asm volatile("cp.async.wait_group 2;" ::: "memory")
#define CPA_WAIT0()  asm volatile("cp.async.wait_group 0;" ::: "memory")

// ---------------- pre-pass kernels ----------------
__global__ __launch_bounds__(256) void presplit_hi(const float4* __restrict__ src,
                                                   uint2* __restrict__ dhi)
{
    int i = blockIdx.x * blockDim.x + threadIdx.x;
    float4 t = src[i];
    dhi[i] = make_uint2(pk2(t.x, t.y), pk2(t.z, t.w));
}

__global__ __launch_bounds__(256) void pmask(const int* __restrict__ mask,
                                             uint32_t* __restrict__ bits)
{
    int idx = blockIdx.x * blockDim.x + threadIdx.x;   // word index
    const int4* m4 = (const int4*)mask + (size_t)idx * 8;
    uint32_t b = 0;
    #pragma unroll
    for (int i = 0; i < 8; ++i) {
        int4 v = m4[i];
        b |= (v.x != 0 ? 1u : 0u) << (i * 4);
        b |= (v.y != 0 ? 1u : 0u) << (i * 4 + 1);
        b |= (v.z != 0 ? 1u : 0u) << (i * 4 + 2);
        b |= (v.w != 0 ? 1u : 0u) << (i * 4 + 3);
    }
    bits[idx] = b;
}

__global__ __launch_bounds__(256, 2)
void attn_mma(float* __restrict__ out, float* __restrict__ p)
{
    extern __shared__ char sm[];
    const uint32_t sb = s2u(sm);
    const int tid = threadIdx.x;
    const int wid = tid >> 5, lane = tid & 31;
    const int rg = wid >> 1;                 // row group (16 rows)
    const int nhalf = wid & 1;               // 32-col half of tile
    const int bh = blockIdx.y;
    const int q0 = blockIdx.x * BQ;

    // cp.async mapping: chunk cc (16B), rows rr, rr+32
    const int cc = tid & 7, rr = tid >> 3;
    const uint32_t dcol = ((uint32_t)cc) << 4;
    const uint32_t drow0 = (uint32_t)rr * 128 + (dcol ^ (((uint32_t)rr & 7) << 4));
    const uint32_t drow1 = (uint32_t)(rr + 32) * 128 + (dcol ^ ((((uint32_t)rr + 32) & 7) << 4));
    const size_t srow0 = (size_t)rr * 128 + cc * 16;
    const size_t srow1 = (size_t)(rr + 32) * 128 + cc * 16;

    const char* khb = (const char*)g_khi + (size_t)bh * S_LEN * 128;
    const char* vhb = (const char*)g_vhi + (size_t)bh * S_LEN * 128;

    // epilogue thread mapping (m16n8 accum layout)
    const int r0l = rg * 16 + (lane >> 2);
    const int coff = (lane & 3) * 2;

    // ldmatrix lane mappings (XOR applied AFTER column adds)
    const int arow = rg * 16 + (lane & 15);
    const uint32_t arowoff = (uint32_t)arow * 128;
    const uint32_t acol0 = ((uint32_t)(lane >> 4)) << 4;
    const uint32_t axor = ((uint32_t)arow & 7) << 4;
    const int nrow = ((lane >> 4) << 3) + (lane & 7);
    const uint32_t nbase = (uint32_t)(nhalf * 32 + nrow) * 128;
    const uint32_t ncol0 = (((uint32_t)lane >> 3) & 1) << 4;
    const uint32_t nxor = ((uint32_t)(nrow & 7)) << 4;
    const int vrow = (((lane >> 3) & 1) << 3) + (lane & 7);
    const uint32_t vbase_off = (uint32_t)(nhalf * 32 + vrow) * 128;
    const uint32_t vcol0 = ((uint32_t)(lane >> 4)) << 4;
    const uint32_t vxor = ((uint32_t)(vrow & 7)) << 4;

    const uint32_t* mb0 = g_mbits + (size_t)(q0 + r0l) * 64 + nhalf;
    const uint32_t* mb1 = mb0 + 8 * 64;

    // ===== prologue: Q hi + pass-A 4-stage KH ring prime =====
    {
        const char* qh = (const char*)g_qhi + ((size_t)bh * S_LEN + q0) * 128;
        cpa16(sb + OFF_QH + drow0, qh + srow0);
        cpa16(sb + OFF_QH + drow1, qh + srow1);
        cpa16(sb + OFF_ST + drow0, khb + srow0);
        cpa16(sb + OFF_ST + drow1, khb + srow1);
        CPA_COMMIT();
        #pragma unroll
        for (int s = 1; s < 3; ++s) {
            const uint32_t st = sb + OFF_ST + (uint32_t)s * 8192;
            const size_t tb = (size_t)s * BKT * 128;
            cpa16(st + drow0, khb + tb + srow0);
            cpa16(st + drow1, khb + tb + srow1);
            CPA_COMMIT();
        }
    }
    CPA_WAIT2();          // Q + stage0 complete
    __syncthreads();

    // ---- hoist Q hi fragments (tile-invariant) into registers
    uint32_t qah[4][4];
    #pragma unroll
    for (int ks = 0; ks < 4; ++ks) {
        const uint32_t ao = arowoff + ((acol0 + (uint32_t)ks * 32) ^ axor);
        ldsm4(sb + OFF_QH + ao, qah[ks]);
    }

    float esum0 = 0.f, esum1 = 0.f;

    // ===== PASS A: approximate row sums (Qh.Kh fp16) =====
    for (int kb = 0; kb < NTILE; ++kb) {
        if (kb) { CPA_WAIT2(); __syncthreads(); }
        const uint32_t st = sb + OFF_ST + (uint32_t)(kb & 3) * 8192;
        const uint32_t w0 = mb0[kb * 2];
        const uint32_t w1 = mb1[kb * 2];

        float acc[4][4];
        #pragma unroll
        for (int i = 0; i < 4; ++i)
            #pragma unroll
            for (int c = 0; c < 4; ++c) acc[i][c] = 0.f;

        #pragma unroll
        for (int ks = 0; ks < 4; ++ks) {
            #pragma unroll
            for (int np = 0; np < 2; ++np) {
                uint32_t bh4[4];
                const uint32_t bo = nbase + (uint32_t)np * 2048 +
                                    ((ncol0 + (uint32_t)ks * 32) ^ nxor);
                ldsm4(st + bo, bh4);
                mma_f16(acc[np * 2], qah[ks], bh4[0], bh4[1]);
                mma_f16(acc[np * 2 + 1], qah[ks], bh4[2], bh4[3]);
            }
        }

        #pragma unroll
        for (int nt = 0; nt < 4; ++nt) {
            const int sh = coff + nt * 8;
            esum0 += ((w0 >> sh) & 1 ? __expf(acc[nt][0] * 0.125f) : 0.f)
                   + ((w0 >> (sh + 1)) & 1 ? __expf(acc[nt][1] * 0.125f) : 0.f);
            esum1 += ((w1 >> sh) & 1 ? __expf(acc[nt][2] * 0.125f) : 0.f)
                   + ((w1 >> (sh + 1)) & 1 ? __expf(acc[nt][3] * 0.125f) : 0.f);
        }

        if (kb + 3 < NTILE) {
            const uint32_t sn = sb + OFF_ST + (uint32_t)((kb + 3) & 3) * 8192;
            const size_t tb = (size_t)(kb + 3) * BKT * 128;
            cpa16(sn + drow0, khb + tb + srow0);
            cpa16(sn + drow1, khb + tb + srow1);
        }
        CPA_COMMIT();                        // keeps group count aligned
    }
    CPA_WAIT0();
    __syncthreads();

    // ===== prime pass-B ring {KH, VH} x3 slots (overlaps reduction) =====
    {
        #pragma unroll
        for (int s = 0; s < 3; ++s) {
            const uint32_t st = sb + OFF_ST + (uint32_t)s * 16384;
            const size_t tb = (size_t)s * BKT * 128;
            cpa16(st + drow0, khb + tb + srow0);          cpa16(st + drow1, khb + tb + srow1);
            cpa16(st + 8192 + drow0, vhb + tb + srow0);   cpa16(st + 8192 + drow1, vhb + tb + srow1);
            CPA_COMMIT();
        }
    }

    // ===== inter-pass: row sums -> inv =====
    esum0 += __shfl_xor_sync(0xffffffffu, esum0, 1);
    esum0 += __shfl_xor_sync(0xffffffffu, esum0, 2);
    esum1 += __shfl_xor_sync(0xffffffffu, esum1, 1);
    esum1 += __shfl_xor_sync(0xffffffffu, esum1, 2);
    float* rsum = (float*)(sm + OFF_RS);
    float* inv_s = (float*)(sm + OFF_INV);
    if ((lane & 3) == 0) {
        rsum[nhalf * 64 + r0l] = esum0;
        rsum[nhalf * 64 + r0l + 8] = esum1;
    }
    __syncthreads();
    if (tid < 64) inv_s[tid] = 1.f / (rsum[tid] + rsum[64 + tid]);
    __syncthreads();
    const float inv0 = inv_s[r0l], inv1 = inv_s[r0l + 8];

    float Oacc[8][4];
    #pragma unroll
    for (int i = 0; i < 8; ++i)
        #pragma unroll
        for (int c = 0; c < 4; ++c) Oacc[i][c] = 0.f;

    // ===== PASS B: S = Qh.Kh ; O += Êh.Vh ; normalized p write =====
    for (int kb = 0; kb < NTILE; ++kb) {
        CPA_WAIT2();
        __syncthreads();
        const uint32_t st = sb + OFF_ST + (uint32_t)(kb & 3) * 16384;
        const uint32_t w0 = mb0[kb * 2];
        const uint32_t w1 = mb1[kb * 2];

        float acc[4][4];
        #pragma unroll
        for (int i = 0; i < 4; ++i)
            #pragma unroll
            for (int c = 0; c < 4; ++c) acc[i][c] = 0.f;

        // ---- GEMM1: S = Qh.Kh  (1 product)
        #pragma unroll
        for (int ks = 0; ks < 4; ++ks) {
            #pragma unroll
            for (int np = 0; np < 2; ++np) {
                uint32_t bh4[4];
                const uint32_t bo = nbase + (uint32_t)np * 2048 +
                                    ((ncol0 + (uint32_t)ks * 32) ^ nxor);
                ldsm4(st + bo, bh4);
                mma_f16(acc[np * 2], qah[ks], bh4[0], bh4[1]);
                mma_f16(acc[np * 2 + 1], qah[ks], bh4[2], bh4[3]);
            }
        }

        // ---- epilogue: ê = exp * inv (normalized), p write, Êh frags
        uint32_t Eh[2][4];
        const int cb = kb * BKT + nhalf * 32 + coff;
        float* prow0 = p + ((size_t)(bh * S_LEN) + q0 + r0l) * S_LEN + cb;
        float* prow1 = prow0 + (size_t)8 * S_LEN;
        #pragma unroll
        for (int nt = 0; nt < 4; ++nt) {
            const int sh = coff + nt * 8;
            float e0 = (w0 >> sh) & 1 ? __expf(acc[nt][0] * 0.125f) * inv0 : 0.f;
            float e1 = (w0 >> (sh + 1)) & 1 ? __expf(acc[nt][1] * 0.125f) * inv0 : 0.f;
            float e2 = (w1 >> sh) & 1 ? __expf(acc[nt][2] * 0.125f) * inv1 : 0.f;
            float e3 = (w1 >> (sh + 1)) & 1 ? __expf(acc[nt][3] * 0.125f) * inv1 : 0.f;
            *(float2*)(prow0 + nt * 8) = make_float2(e0, e1);
            *(float2*)(prow1 + nt * 8) = make_float2(e2, e3);
            const int kk = nt >> 1, sl = (nt & 1) * 2;
            Eh[kk][sl + 0] = pk2(e0, e1);
            Eh[kk][sl + 1] = pk2(e2, e3);
        }

        // ---- GEMM2: O += Êh.Vh  (1 product)
        #pragma unroll
        for (int kk = 0; kk < 2; ++kk) {
            const uint32_t vrt = vbase_off + (uint32_t)kk * 2048;
            #pragma unroll
            for (int dt2 = 0; dt2 < 4; ++dt2) {
                uint32_t vh4[4];
                const uint32_t o = vrt + ((vcol0 + (uint32_t)dt2 * 32) ^ vxor);
                ldsm4t(st + 8192 + o, vh4);
                mma_f16(Oacc[dt2 * 2], Eh[kk], vh4[0], vh4[1]);
                mma_f16(Oacc[dt2 * 2 + 1], Eh[kk], vh4[2], vh4[3]);
            }
        }

        if (kb + 3 < NTILE) {
            const uint32_t sn = sb + OFF_ST + (uint32_t)((kb + 3) & 3) * 16384;
            const size_t tb = (size_t)(kb + 3) * BKT * 128;
            cpa16(sn + drow0, khb + tb + srow0);          cpa16(sn + drow1, khb + tb + srow1);
            cpa16(sn + 8192 + drow0, vhb + tb + srow0);   cpa16(sn + 8192 + drow1, vhb + tb + srow1);
        }
        CPA_COMMIT();
    }
    CPA_WAIT0();
    __syncthreads();      // ring reads done; smem reusable

    // ---- O combine across nhalf halves (already normalized) and store
    float* Osm = (float*)(sm + OFF_OSM);
    if (nhalf == 1) {
        #pragma unroll
        for (int dt = 0; dt < 8; ++dt) {
            *(float2*)&Osm[r0l * 64 + dt * 8 + coff] = make_float2(Oacc[dt][0], Oacc[dt][1]);
            *(float2*)&Osm[(r0l + 8) * 64 + dt * 8 + coff] = make_float2(Oacc[dt][2], Oacc[dt][3]);
        }
    }
    __syncthreads();
    if (nhalf == 0) {
        float* orow0 = out + ((size_t)(bh * S_LEN) + q0 + r0l) * DH + coff;
        float* orow1 = orow0 + 8 * DH;
        #pragma unroll
        for (int dt = 0; dt < 8; ++dt) {
            float2 a0 = *(float2*)&Osm[r0l * 64 + dt * 8 + coff];
            float2 a1 = *(float2*)&Osm[(r0l + 8) * 64 + dt * 8 + coff];
            *(float2*)(orow0 + dt * 8) = make_float2(Oacc[dt][0] + a0.x, Oacc[dt][1] + a0.y);
            *(float2*)(orow1 + dt * 8) = make_float2(Oacc[dt][2] + a1.x, Oacc[dt][3] + a1.y);
        }
    }
}

extern "C" void kernel_launch(void* const* d_in, const int* in_sizes, int n_in,
                              void* d_out, int out_size)
{
    const float* q    = (const float*)d_in[0];
    const float* k    = (const float*)d_in[1];
    const float* v    = (const float*)d_in[2];
    const int*   mask = (const int*)d_in[3];

    float* out = (float*)d_out;
    float* p   = out + NELEM;

    uint2 *qhi, *khi, *vhi;
    uint32_t* mbits;
    cudaGetSymbolAddress((void**)&qhi, g_qhi);
    cudaGetSymbolAddress((void**)&khi, g_khi);
    cudaGetSymbolAddress((void**)&vhi, g_vhi);
    cudaGetSymbolAddress((void**)&mbits, g_mbits);

    const unsigned gpre = (unsigned)(NELEM / 4 / 256);
    presplit_hi<<<gpre, 256>>>((const float4*)q, qhi);
    presplit_hi<<<gpre, 256>>>((const float4*)k, khi);
    presplit_hi<<<gpre, 256>>>((const float4*)v, vhi);
    pmask<<<(unsigned)((size_t)S_LEN * (S_LEN / 32) / 256), 256>>>(mask, mbits);

    cudaFuncSetAttribute(attn_mma, cudaFuncAttributeMaxDynamicSharedMemorySize, SMEM_SZ);
    dim3 g1(S_LEN / BQ, BHN);
    attn_mma<<<g1, 256, SMEM_SZ>>>(out, p);
}